// round 1
// baseline (speedup 1.0000x reference)
#include <cuda_runtime.h>

#define NB 4
#define NS 2048
#define NF 512
#define NH 8
#define NDK 64
#define NDV 64
#define NFILT 512
#define NM (NB*NS)

// Scratch (device globals: no allocation allowed)
__device__ float g_q[(size_t)NB*NH*NS*NDK];
__device__ float g_k[(size_t)NB*NH*NS*NDK];
__device__ float g_v[(size_t)NB*NH*NS*NDV];
__device__ float g_concat[(size_t)NB*NS*NH*NDV];

// ---------------------------------------------------------------------------
// Per-head projection GEMM: out[b,h,s,:] = X[b,s,:] @ W[h] + bias[h]
// X: [B*S, F], W: [H, F, 64], out: [B, H, S, 64]
// grid: (NM/64, H), block: 256
// ---------------------------------------------------------------------------
__global__ __launch_bounds__(256) void proj_kernel(
    const float* __restrict__ X, const float* __restrict__ W,
    const float* __restrict__ bias, float* __restrict__ out)
{
    __shared__ float As[16][68];
    __shared__ float Bs[16][68];
    const int h  = blockIdx.y;
    const int m0 = blockIdx.x * 64;
    const int tid = threadIdx.x;
    const int tx = tid & 15, ty = tid >> 4;
    const float* Wh = W + (size_t)h * NF * NDK;
    float acc[4][4] = {};
    const int arow = tid >> 2, akk = (tid & 3) << 2;
    const int brow = tid >> 4, bcc = (tid & 15) << 2;

    for (int k0 = 0; k0 < NF; k0 += 16) {
        float4 a = *(const float4*)(X + (size_t)(m0 + arow) * NF + k0 + akk);
        As[akk + 0][arow] = a.x; As[akk + 1][arow] = a.y;
        As[akk + 2][arow] = a.z; As[akk + 3][arow] = a.w;
        *(float4*)&Bs[brow][bcc] =
            *(const float4*)(Wh + (size_t)(k0 + brow) * NDK + bcc);
        __syncthreads();
        #pragma unroll
        for (int kk = 0; kk < 16; kk++) {
            float4 ra4 = *(const float4*)&As[kk][ty << 2];
            float4 rb4 = *(const float4*)&Bs[kk][tx << 2];
            float rav[4] = {ra4.x, ra4.y, ra4.z, ra4.w};
            float rbv[4] = {rb4.x, rb4.y, rb4.z, rb4.w};
            #pragma unroll
            for (int i = 0; i < 4; i++)
                #pragma unroll
                for (int j = 0; j < 4; j++)
                    acc[i][j] += rav[i] * rbv[j];
        }
        __syncthreads();
    }
    const int bb = m0 / NS, s0 = m0 % NS;
    float4 bi4 = *(const float4*)(bias + h * NDK + (tx << 2));
    float biv[4] = {bi4.x, bi4.y, bi4.z, bi4.w};
    #pragma unroll
    for (int i = 0; i < 4; i++) {
        int row = (ty << 2) + i;
        float* orow = out + ((size_t)(bb * NH + h) * NS + s0 + row) * NDK;
        float4 o = make_float4(acc[i][0] + biv[0], acc[i][1] + biv[1],
                               acc[i][2] + biv[2], acc[i][3] + biv[3]);
        *(float4*)(orow + (tx << 2)) = o;
    }
}

// ---------------------------------------------------------------------------
// Output GEMM: C = A[NM,512] @ W[512,512] + bias
// grid: (NM/64, NFILT/64), block: 256
// ---------------------------------------------------------------------------
__global__ __launch_bounds__(256) void out_gemm(
    const float* __restrict__ A, const float* __restrict__ W,
    const float* __restrict__ bias, float* __restrict__ C)
{
    __shared__ float As[16][68];
    __shared__ float Bs[16][68];
    const int n0 = blockIdx.y * 64;
    const int m0 = blockIdx.x * 64;
    const int tid = threadIdx.x;
    const int tx = tid & 15, ty = tid >> 4;
    float acc[4][4] = {};
    const int arow = tid >> 2, akk = (tid & 3) << 2;
    const int brow = tid >> 4, bcc = (tid & 15) << 2;

    for (int k0 = 0; k0 < NFILT; k0 += 16) {
        float4 a = *(const float4*)(A + (size_t)(m0 + arow) * NFILT + k0 + akk);
        As[akk + 0][arow] = a.x; As[akk + 1][arow] = a.y;
        As[akk + 2][arow] = a.z; As[akk + 3][arow] = a.w;
        *(float4*)&Bs[brow][bcc] =
            *(const float4*)(W + (size_t)(k0 + brow) * NFILT + n0 + bcc);
        __syncthreads();
        #pragma unroll
        for (int kk = 0; kk < 16; kk++) {
            float4 ra4 = *(const float4*)&As[kk][ty << 2];
            float4 rb4 = *(const float4*)&Bs[kk][tx << 2];
            float rav[4] = {ra4.x, ra4.y, ra4.z, ra4.w};
            float rbv[4] = {rb4.x, rb4.y, rb4.z, rb4.w};
            #pragma unroll
            for (int i = 0; i < 4; i++)
                #pragma unroll
                for (int j = 0; j < 4; j++)
                    acc[i][j] += rav[i] * rbv[j];
        }
        __syncthreads();
    }
    float4 bi4 = *(const float4*)(bias + n0 + (tx << 2));
    float biv[4] = {bi4.x, bi4.y, bi4.z, bi4.w};
    #pragma unroll
    for (int i = 0; i < 4; i++) {
        int row = (ty << 2) + i;
        float4 o = make_float4(acc[i][0] + biv[0], acc[i][1] + biv[1],
                               acc[i][2] + biv[2], acc[i][3] + biv[3]);
        *(float4*)(C + (size_t)(m0 + row) * NFILT + n0 + (tx << 2)) = o;
    }
}

// ---------------------------------------------------------------------------
// Flash attention: one CTA per (b,h, 64-query tile).
// q,k,v: [B,H,S,64]. Writes concat layout [B,S,H*64].
// Smem: Qs (d-major), KPs (K d-major, then reused as P row-major), Vs (t-major)
// = 3 * 64*64*4 = 49152 B (static limit, exact).
// grid: (NS/64, B*H), block: 256
// ---------------------------------------------------------------------------
__global__ __launch_bounds__(256) void attn_kernel(
    const float* __restrict__ q, const float* __restrict__ k,
    const float* __restrict__ v, float* __restrict__ concat)
{
    __shared__ float Qs[64 * 64];   // Qs[d*64 + row], pre-scaled by 1/sqrt(dk)
    __shared__ float KPs[64 * 64];  // K: [d*64 + col]; later P: [row*64 + t]
    __shared__ float Vs[64 * 64];   // Vs[t*64 + d]
    const int bh = blockIdx.y;                 // = b*H + h
    const int bb = bh / NH, hh = bh % NH;
    const int s0 = blockIdx.x * 64;
    const int tid = threadIdx.x;
    const int tx = tid & 15, ty = tid >> 4;
    const size_t base = (size_t)bh * NS * 64;

    // Load + transpose + scale Q tile
    {
        const int row = tid >> 2, dd = (tid & 3) << 4;
        const float* src = q + base + (size_t)(s0 + row) * 64 + dd;
        #pragma unroll
        for (int u = 0; u < 4; u++) {
            float4 a = *(const float4*)(src + u * 4);
            Qs[(dd + u * 4 + 0) * 64 + row] = a.x * 0.125f;
            Qs[(dd + u * 4 + 1) * 64 + row] = a.y * 0.125f;
            Qs[(dd + u * 4 + 2) * 64 + row] = a.z * 0.125f;
            Qs[(dd + u * 4 + 3) * 64 + row] = a.w * 0.125f;
        }
    }

    float m_i[4], l_i[4], O[4][4];
    #pragma unroll
    for (int i = 0; i < 4; i++) {
        m_i[i] = -1e30f; l_i[i] = 0.0f;
        #pragma unroll
        for (int j = 0; j < 4; j++) O[i][j] = 0.0f;
    }

    for (int kt = 0; kt < NS; kt += 64) {
        __syncthreads();  // protect KPs(P)/Vs of previous iter (and Q stores, iter 0)
        // Load K (transposed, d-major) and V (natural)
        {
            const int row = tid >> 2, dd = (tid & 3) << 4;
            const float* ks = k + base + (size_t)(kt + row) * 64 + dd;
            const float* vs = v + base + (size_t)(kt + row) * 64 + dd;
            #pragma unroll
            for (int u = 0; u < 4; u++) {
                float4 a = *(const float4*)(ks + u * 4);
                KPs[(dd + u * 4 + 0) * 64 + row] = a.x;
                KPs[(dd + u * 4 + 1) * 64 + row] = a.y;
                KPs[(dd + u * 4 + 2) * 64 + row] = a.z;
                KPs[(dd + u * 4 + 3) * 64 + row] = a.w;
                *(float4*)&Vs[row * 64 + dd + u * 4] = *(const float4*)(vs + u * 4);
            }
        }
        __syncthreads();

        // S = (Q*scale) @ K^T  (4x4 fragment per thread)
        float sacc[4][4] = {};
        #pragma unroll 16
        for (int d = 0; d < 64; d++) {
            float4 ra4 = *(const float4*)&Qs[d * 64 + (ty << 2)];
            float4 rb4 = *(const float4*)&KPs[d * 64 + (tx << 2)];
            float rav[4] = {ra4.x, ra4.y, ra4.z, ra4.w};
            float rbv[4] = {rb4.x, rb4.y, rb4.z, rb4.w};
            #pragma unroll
            for (int i = 0; i < 4; i++)
                #pragma unroll
                for (int j = 0; j < 4; j++)
                    sacc[i][j] += rav[i] * rbv[j];
        }

        // Online softmax, entirely in registers (rows are 16-lane groups)
        #pragma unroll
        for (int i = 0; i < 4; i++) {
            float rmax = fmaxf(fmaxf(sacc[i][0], sacc[i][1]),
                               fmaxf(sacc[i][2], sacc[i][3]));
            rmax = fmaxf(rmax, __shfl_xor_sync(0xffffffffu, rmax, 1));
            rmax = fmaxf(rmax, __shfl_xor_sync(0xffffffffu, rmax, 2));
            rmax = fmaxf(rmax, __shfl_xor_sync(0xffffffffu, rmax, 4));
            rmax = fmaxf(rmax, __shfl_xor_sync(0xffffffffu, rmax, 8));
            float mnew = fmaxf(m_i[i], rmax);
            float alpha = __expf(m_i[i] - mnew);
            float rsum = 0.0f;
            #pragma unroll
            for (int j = 0; j < 4; j++) {
                float p = __expf(sacc[i][j] - mnew);
                sacc[i][j] = p;
                rsum += p;
            }
            rsum += __shfl_xor_sync(0xffffffffu, rsum, 1);
            rsum += __shfl_xor_sync(0xffffffffu, rsum, 2);
            rsum += __shfl_xor_sync(0xffffffffu, rsum, 4);
            rsum += __shfl_xor_sync(0xffffffffu, rsum, 8);
            m_i[i] = mnew;
            l_i[i] = l_i[i] * alpha + rsum;
            #pragma unroll
            for (int j = 0; j < 4; j++) O[i][j] *= alpha;
        }
        __syncthreads();  // everyone done reading KPs as K

        // Store P into KPs (row-major)
        #pragma unroll
        for (int i = 0; i < 4; i++)
            *(float4*)&KPs[((ty << 2) + i) * 64 + (tx << 2)] =
                make_float4(sacc[i][0], sacc[i][1], sacc[i][2], sacc[i][3]);
        __syncthreads();

        // O += P @ V  (float4 on both operands)
        #pragma unroll 4
        for (int t0 = 0; t0 < 64; t0 += 4) {
            float rpv[4][4];
            #pragma unroll
            for (int i = 0; i < 4; i++) {
                float4 rp = *(const float4*)&KPs[((ty << 2) + i) * 64 + t0];
                rpv[i][0] = rp.x; rpv[i][1] = rp.y; rpv[i][2] = rp.z; rpv[i][3] = rp.w;
            }
            #pragma unroll
            for (int u = 0; u < 4; u++) {
                float4 rv4 = *(const float4*)&Vs[(t0 + u) * 64 + (tx << 2)];
                float rvv[4] = {rv4.x, rv4.y, rv4.z, rv4.w};
                #pragma unroll
                for (int i = 0; i < 4; i++) {
                    float p = rpv[i][u];
                    #pragma unroll
                    for (int j = 0; j < 4; j++)
                        O[i][j] += p * rvv[j];
                }
            }
        }
    }

    // Normalize and write to concat [B, S, H*DV]
    #pragma unroll
    for (int i = 0; i < 4; i++) {
        int row = (ty << 2) + i;
        float inv = 1.0f / l_i[i];
        float4 o = make_float4(O[i][0] * inv, O[i][1] * inv,
                               O[i][2] * inv, O[i][3] * inv);
        *(float4*)(concat + ((size_t)bb * NS + s0 + row) * (NH * NDV)
                          + hh * NDV + (tx << 2)) = o;
    }
}

// ---------------------------------------------------------------------------
extern "C" void kernel_launch(void* const* d_in, const int* in_sizes, int n_in,
                              void* d_out, int out_size)
{
    (void)in_sizes; (void)n_in; (void)out_size;
    const float* x_q = (const float*)d_in[0];
    const float* x_k = (const float*)d_in[1];
    const float* x_v = (const float*)d_in[2];
    const float* Wq  = (const float*)d_in[3];
    const float* bq  = (const float*)d_in[4];
    const float* Wk  = (const float*)d_in[5];
    const float* bk  = (const float*)d_in[6];
    const float* Wv  = (const float*)d_in[7];
    const float* bv  = (const float*)d_in[8];
    const float* Wo  = (const float*)d_in[9];
    const float* bo  = (const float*)d_in[10];
    float* out = (float*)d_out;

    float *qp, *kp, *vp, *cp;
    cudaGetSymbolAddress((void**)&qp, g_q);
    cudaGetSymbolAddress((void**)&kp, g_k);
    cudaGetSymbolAddress((void**)&vp, g_v);
    cudaGetSymbolAddress((void**)&cp, g_concat);

    dim3 pgrid(NM / 64, NH);
    proj_kernel<<<pgrid, 256>>>(x_q, Wq, bq, qp);
    proj_kernel<<<pgrid, 256>>>(x_k, Wk, bk, kp);
    proj_kernel<<<pgrid, 256>>>(x_v, Wv, bv, vp);

    attn_kernel<<<dim3(NS / 64, NB * NH), 256>>>(qp, kp, vp, cp);

    out_gemm<<<dim3(NM / 64, NFILT / 64), 256>>>(cp, Wo, bo, out);
}

// round 2
// speedup vs baseline: 1.0726x; 1.0726x over previous
#include <cuda_runtime.h>

#define NB 4
#define NS 2048
#define NF 512
#define NH 8
#define ND 64
#define NFILT 512
#define NM (NB*NS)

// Scratch (device globals: no allocation allowed)
__device__ float g_q[(size_t)NB*NH*NS*ND];
__device__ float g_k[(size_t)NB*NH*NS*ND];
__device__ float g_v[(size_t)NB*NH*NS*ND];
__device__ float g_concat[(size_t)NB*NS*NH*ND];

// ===========================================================================
// Warp/lane decomposition shared by all kernels:
//   256 threads = 8 warps in 4(row) x 2(col) grid
//   32 lanes    = 4(row) x 8(col) grid
//   thread fragment: 8x8 (GEMM/S) rows = wr*32+lr*8, cols = wc*64+lc*8
// ===========================================================================

// ---------------------------------------------------------------------------
// Per-head projection GEMM: out[b,h,s,:] = X[b,s,:] @ W[h] + bias[h]
// X: [B*S, F], W: [H, F, 64], out: [B, H, S, 64]
// CTA tile 128(M) x 128(N = 2 heads) x 16(K). grid: (NM/128, H/2), block 256
// ---------------------------------------------------------------------------
__global__ __launch_bounds__(256, 2) void proj_kernel(
    const float* __restrict__ X, const float* __restrict__ W,
    const float* __restrict__ bias, float* __restrict__ out)
{
    __shared__ float As[16 * 128];
    __shared__ float Bs[16 * 128];
    const int tid = threadIdx.x;
    const int w = tid >> 5, lane = tid & 31;
    const int wr = w & 3, wc = w >> 2;
    const int lr = lane >> 3, lc = lane & 7;
    const int row0 = wr * 32 + lr * 8;
    const int col0 = wc * 64 + lc * 8;
    const int m0 = blockIdx.x * 128;
    const int h0 = blockIdx.y * 2;

    const int am = tid & 127;
    const int ak = (tid >> 7) * 8;
    const float* Aptr = X + (size_t)(m0 + am) * NF + ak;
    const int bk = tid >> 4;        // 0..15
    const int bn = (tid & 15) * 8;  // 0..120
    const int bhead = h0 + (bn >> 6);
    const float* Bptr = W + (size_t)bhead * NF * ND + (size_t)bk * ND + (bn & 63);

    float acc[8][8] = {};
    for (int k0 = 0; k0 < NF; k0 += 16) {
        float4 a0 = *(const float4*)(Aptr + k0);
        float4 a1 = *(const float4*)(Aptr + k0 + 4);
        float4 b0 = *(const float4*)(Bptr + (size_t)k0 * ND);
        float4 b1 = *(const float4*)(Bptr + (size_t)k0 * ND + 4);
        __syncthreads();
        As[(ak + 0) * 128 + am] = a0.x; As[(ak + 1) * 128 + am] = a0.y;
        As[(ak + 2) * 128 + am] = a0.z; As[(ak + 3) * 128 + am] = a0.w;
        As[(ak + 4) * 128 + am] = a1.x; As[(ak + 5) * 128 + am] = a1.y;
        As[(ak + 6) * 128 + am] = a1.z; As[(ak + 7) * 128 + am] = a1.w;
        *(float4*)&Bs[bk * 128 + bn] = b0;
        *(float4*)&Bs[bk * 128 + bn + 4] = b1;
        __syncthreads();
        #pragma unroll
        for (int kk = 0; kk < 16; kk++) {
            float4 x0 = *(const float4*)&As[kk * 128 + row0];
            float4 x1 = *(const float4*)&As[kk * 128 + row0 + 4];
            float4 y0 = *(const float4*)&Bs[kk * 128 + col0];
            float4 y1 = *(const float4*)&Bs[kk * 128 + col0 + 4];
            float xa[8] = {x0.x, x0.y, x0.z, x0.w, x1.x, x1.y, x1.z, x1.w};
            float yb[8] = {y0.x, y0.y, y0.z, y0.w, y1.x, y1.y, y1.z, y1.w};
            #pragma unroll
            for (int i = 0; i < 8; i++)
                #pragma unroll
                for (int j = 0; j < 8; j++)
                    acc[i][j] += xa[i] * yb[j];
        }
    }
    const int head = h0 + wc;
    const float* bi = bias + head * ND + lc * 8;
    float4 bv0 = *(const float4*)bi;
    float4 bv1 = *(const float4*)(bi + 4);
    float bv[8] = {bv0.x, bv0.y, bv0.z, bv0.w, bv1.x, bv1.y, bv1.z, bv1.w};
    const int mm = m0 + row0;
    const int bb = mm / NS, ss = mm % NS;
    float* ob = out + ((size_t)(bb * NH + head) * NS + ss) * ND + lc * 8;
    #pragma unroll
    for (int i = 0; i < 8; i++) {
        *(float4*)(ob + (size_t)i * ND) =
            make_float4(acc[i][0] + bv[0], acc[i][1] + bv[1],
                        acc[i][2] + bv[2], acc[i][3] + bv[3]);
        *(float4*)(ob + (size_t)i * ND + 4) =
            make_float4(acc[i][4] + bv[4], acc[i][5] + bv[5],
                        acc[i][6] + bv[6], acc[i][7] + bv[7]);
    }
}

// ---------------------------------------------------------------------------
// Output GEMM: C = A[NM,512] @ W[512,512] + bias. Tile 128x128x16.
// grid: (NM/128, NFILT/128), block 256
// ---------------------------------------------------------------------------
__global__ __launch_bounds__(256, 2) void out_gemm(
    const float* __restrict__ A, const float* __restrict__ W,
    const float* __restrict__ bias, float* __restrict__ C)
{
    __shared__ float As[16 * 128];
    __shared__ float Bs[16 * 128];
    const int tid = threadIdx.x;
    const int w = tid >> 5, lane = tid & 31;
    const int wr = w & 3, wc = w >> 2;
    const int lr = lane >> 3, lc = lane & 7;
    const int row0 = wr * 32 + lr * 8;
    const int col0 = wc * 64 + lc * 8;
    const int m0 = blockIdx.x * 128;
    const int n0 = blockIdx.y * 128;

    const int am = tid & 127;
    const int ak = (tid >> 7) * 8;
    const float* Aptr = A + (size_t)(m0 + am) * NFILT + ak;
    const int bk = tid >> 4;
    const int bn = (tid & 15) * 8;
    const float* Bptr = W + (size_t)bk * NFILT + n0 + bn;

    float acc[8][8] = {};
    for (int k0 = 0; k0 < NFILT; k0 += 16) {
        float4 a0 = *(const float4*)(Aptr + k0);
        float4 a1 = *(const float4*)(Aptr + k0 + 4);
        float4 b0 = *(const float4*)(Bptr + (size_t)k0 * NFILT);
        float4 b1 = *(const float4*)(Bptr + (size_t)k0 * NFILT + 4);
        __syncthreads();
        As[(ak + 0) * 128 + am] = a0.x; As[(ak + 1) * 128 + am] = a0.y;
        As[(ak + 2) * 128 + am] = a0.z; As[(ak + 3) * 128 + am] = a0.w;
        As[(ak + 4) * 128 + am] = a1.x; As[(ak + 5) * 128 + am] = a1.y;
        As[(ak + 6) * 128 + am] = a1.z; As[(ak + 7) * 128 + am] = a1.w;
        *(float4*)&Bs[bk * 128 + bn] = b0;
        *(float4*)&Bs[bk * 128 + bn + 4] = b1;
        __syncthreads();
        #pragma unroll
        for (int kk = 0; kk < 16; kk++) {
            float4 x0 = *(const float4*)&As[kk * 128 + row0];
            float4 x1 = *(const float4*)&As[kk * 128 + row0 + 4];
            float4 y0 = *(const float4*)&Bs[kk * 128 + col0];
            float4 y1 = *(const float4*)&Bs[kk * 128 + col0 + 4];
            float xa[8] = {x0.x, x0.y, x0.z, x0.w, x1.x, x1.y, x1.z, x1.w};
            float yb[8] = {y0.x, y0.y, y0.z, y0.w, y1.x, y1.y, y1.z, y1.w};
            #pragma unroll
            for (int i = 0; i < 8; i++)
                #pragma unroll
                for (int j = 0; j < 8; j++)
                    acc[i][j] += xa[i] * yb[j];
        }
    }
    const float* bi = bias + n0 + col0;
    float4 bv0 = *(const float4*)bi;
    float4 bv1 = *(const float4*)(bi + 4);
    float bv[8] = {bv0.x, bv0.y, bv0.z, bv0.w, bv1.x, bv1.y, bv1.z, bv1.w};
    float* cb = C + (size_t)(m0 + row0) * NFILT + n0 + col0;
    #pragma unroll
    for (int i = 0; i < 8; i++) {
        *(float4*)(cb + (size_t)i * NFILT) =
            make_float4(acc[i][0] + bv[0], acc[i][1] + bv[1],
                        acc[i][2] + bv[2], acc[i][3] + bv[3]);
        *(float4*)(cb + (size_t)i * NFILT + 4) =
            make_float4(acc[i][4] + bv[4], acc[i][5] + bv[5],
                        acc[i][6] + bv[6], acc[i][7] + bv[7]);
    }
}

// ---------------------------------------------------------------------------
// Flash attention: 128-query x 128-key tiles, 8x8 S-fragments, P in smem
// (XOR-swizzled by lane-row so PV a-reads are conflict-free).
// smem: Qs[64][128] | KP[128][128] (K in first half, P full) | Vs[128][64]
//       | redm[2][128] | reds[2][128]   = 133120 B dynamic
// grid: (NS/128, B*H), block 256
// ---------------------------------------------------------------------------
__global__ __launch_bounds__(256, 1) void attn_kernel(
    const float* __restrict__ q, const float* __restrict__ k,
    const float* __restrict__ v, float* __restrict__ concat)
{
    extern __shared__ float sm[];
    float* Qs   = sm;                    // 8192
    float* KP   = sm + 8192;             // 16384
    float* Vs   = sm + 8192 + 16384;     // 8192
    float* redm = Vs + 8192;             // 256
    float* reds = redm + 256;            // 256

    const int tid = threadIdx.x;
    const int w = tid >> 5, lane = tid & 31;
    const int wr = w & 3, wc = w >> 2;
    const int lr = lane >> 3, lc = lane & 7;
    const int row0 = wr * 32 + lr * 8;
    const int colS = wc * 64 + lc * 8;
    const int colO = wc * 32 + lc * 4;
    const int swz = lr << 2;

    const int bh = blockIdx.y, bb = bh >> 3, hh = bh & 7;
    const int s0 = blockIdx.x * 128;
    const float* qb = q + (size_t)bh * NS * ND;
    const float* kb = k + (size_t)bh * NS * ND;
    const float* vb = v + (size_t)bh * NS * ND;

    const int t = tid & 127;
    const int dh = (tid >> 7) * 32;

    // Load Q tile transposed (d-major) and pre-scaled by 1/sqrt(64)
    {
        const float* src = qb + (size_t)(s0 + t) * ND + dh;
        #pragma unroll
        for (int u = 0; u < 8; u++) {
            float4 a = *(const float4*)(src + u * 4);
            Qs[(dh + u * 4 + 0) * 128 + t] = a.x * 0.125f;
            Qs[(dh + u * 4 + 1) * 128 + t] = a.y * 0.125f;
            Qs[(dh + u * 4 + 2) * 128 + t] = a.z * 0.125f;
            Qs[(dh + u * 4 + 3) * 128 + t] = a.w * 0.125f;
        }
    }

    float m_i[8], l_i[8], O[8][4];
    #pragma unroll
    for (int i = 0; i < 8; i++) {
        m_i[i] = -1e30f; l_i[i] = 0.0f;
        O[i][0] = O[i][1] = O[i][2] = O[i][3] = 0.0f;
    }

    for (int kt = 0; kt < NS; kt += 128) {
        __syncthreads();  // prior PV reads of KP/Vs done (covers Q stores on iter 0)
        // K tile transposed (d-major) into first half of KP
        {
            const float* src = kb + (size_t)(kt + t) * ND + dh;
            #pragma unroll
            for (int u = 0; u < 8; u++) {
                float4 a = *(const float4*)(src + u * 4);
                KP[(dh + u * 4 + 0) * 128 + t] = a.x;
                KP[(dh + u * 4 + 1) * 128 + t] = a.y;
                KP[(dh + u * 4 + 2) * 128 + t] = a.z;
                KP[(dh + u * 4 + 3) * 128 + t] = a.w;
            }
        }
        // V tile, straight vectorized copy
        {
            const float4* src = (const float4*)(vb + (size_t)kt * ND);
            float4* dst = (float4*)Vs;
            #pragma unroll
            for (int i2 = 0; i2 < 8; i2++) dst[tid + i2 * 256] = src[tid + i2 * 256];
        }
        __syncthreads();

        // S = (Q*scale) @ K^T : 8x8 fragment
        float sacc[8][8] = {};
        #pragma unroll 8
        for (int d = 0; d < 64; d++) {
            float4 x0 = *(const float4*)&Qs[d * 128 + row0];
            float4 x1 = *(const float4*)&Qs[d * 128 + row0 + 4];
            float4 y0 = *(const float4*)&KP[d * 128 + colS];
            float4 y1 = *(const float4*)&KP[d * 128 + colS + 4];
            float xa[8] = {x0.x, x0.y, x0.z, x0.w, x1.x, x1.y, x1.z, x1.w};
            float yb[8] = {y0.x, y0.y, y0.z, y0.w, y1.x, y1.y, y1.z, y1.w};
            #pragma unroll
            for (int i = 0; i < 8; i++)
                #pragma unroll
                for (int j = 0; j < 8; j++)
                    sacc[i][j] += xa[i] * yb[j];
        }

        // Row max: in-thread -> across lc (shfl) -> across wc (smem)
        float pm[8];
        #pragma unroll
        for (int i = 0; i < 8; i++) {
            float r = fmaxf(fmaxf(fmaxf(sacc[i][0], sacc[i][1]),
                                  fmaxf(sacc[i][2], sacc[i][3])),
                            fmaxf(fmaxf(sacc[i][4], sacc[i][5]),
                                  fmaxf(sacc[i][6], sacc[i][7])));
            r = fmaxf(r, __shfl_xor_sync(0xffffffffu, r, 1));
            r = fmaxf(r, __shfl_xor_sync(0xffffffffu, r, 2));
            r = fmaxf(r, __shfl_xor_sync(0xffffffffu, r, 4));
            pm[i] = r;
        }
        if (lc == 0) {
            #pragma unroll
            for (int i = 0; i < 8; i++) redm[wc * 128 + row0 + i] = pm[i];
        }
        __syncthreads();

        float alpha[8];
        #pragma unroll
        for (int i = 0; i < 8; i++) {
            float mt = fmaxf(redm[row0 + i], redm[128 + row0 + i]);
            float mn = fmaxf(m_i[i], mt);
            alpha[i] = __expf(m_i[i] - mn);
            m_i[i] = mn;
        }
        // exponentiate + row-sum partials
        float ps[8];
        #pragma unroll
        for (int i = 0; i < 8; i++) {
            float s = 0.0f;
            #pragma unroll
            for (int j = 0; j < 8; j++) {
                float p = __expf(sacc[i][j] - m_i[i]);
                sacc[i][j] = p;
                s += p;
            }
            s += __shfl_xor_sync(0xffffffffu, s, 1);
            s += __shfl_xor_sync(0xffffffffu, s, 2);
            s += __shfl_xor_sync(0xffffffffu, s, 4);
            ps[i] = s;
        }
        if (lc == 0) {
            #pragma unroll
            for (int i = 0; i < 8; i++) reds[wc * 128 + row0 + i] = ps[i];
        }
        // Store P (row-major, column index XOR-swizzled by lr*4)
        #pragma unroll
        for (int i = 0; i < 8; i++) {
            int r = row0 + i;
            *(float4*)&KP[r * 128 + ((colS) ^ swz)] =
                make_float4(sacc[i][0], sacc[i][1], sacc[i][2], sacc[i][3]);
            *(float4*)&KP[r * 128 + ((colS + 4) ^ swz)] =
                make_float4(sacc[i][4], sacc[i][5], sacc[i][6], sacc[i][7]);
        }
        // Rescale O accumulators
        #pragma unroll
        for (int i = 0; i < 8; i++) {
            O[i][0] *= alpha[i]; O[i][1] *= alpha[i];
            O[i][2] *= alpha[i]; O[i][3] *= alpha[i];
        }
        __syncthreads();
        #pragma unroll
        for (int i = 0; i < 8; i++)
            l_i[i] = l_i[i] * alpha[i] + reds[row0 + i] + reds[128 + row0 + i];

        // O += P @ V : fragment 8 rows x 4 dv cols
        #pragma unroll 4
        for (int t0 = 0; t0 < 128; t0 += 4) {
            const int tx = t0 ^ swz;
            float pa[8][4];
            #pragma unroll
            for (int i = 0; i < 8; i++) {
                float4 p4 = *(const float4*)&KP[(row0 + i) * 128 + tx];
                pa[i][0] = p4.x; pa[i][1] = p4.y; pa[i][2] = p4.z; pa[i][3] = p4.w;
            }
            #pragma unroll
            for (int tt = 0; tt < 4; tt++) {
                float4 v4 = *(const float4*)&Vs[(t0 + tt) * 64 + colO];
                #pragma unroll
                for (int i = 0; i < 8; i++) {
                    float p = pa[i][tt];
                    O[i][0] += p * v4.x; O[i][1] += p * v4.y;
                    O[i][2] += p * v4.z; O[i][3] += p * v4.w;
                }
            }
        }
    }

    // Normalize, write concat [B, S, H*DV]
    float* ob = concat + ((size_t)bb * NS + s0 + row0) * (NH * ND) + hh * ND + colO;
    #pragma unroll
    for (int i = 0; i < 8; i++) {
        float inv = 1.0f / l_i[i];
        *(float4*)(ob + (size_t)i * (NH * ND)) =
            make_float4(O[i][0] * inv, O[i][1] * inv, O[i][2] * inv, O[i][3] * inv);
    }
}

// ---------------------------------------------------------------------------
#define ATTN_SMEM ((8192 + 16384 + 8192 + 512) * 4)

extern "C" void kernel_launch(void* const* d_in, const int* in_sizes, int n_in,
                              void* d_out, int out_size)
{
    (void)in_sizes; (void)n_in; (void)out_size;
    const float* x_q = (const float*)d_in[0];
    const float* x_k = (const float*)d_in[1];
    const float* x_v = (const float*)d_in[2];
    const float* Wq  = (const float*)d_in[3];
    const float* bq  = (const float*)d_in[4];
    const float* Wk  = (const float*)d_in[5];
    const float* bk  = (const float*)d_in[6];
    const float* Wv  = (const float*)d_in[7];
    const float* bv  = (const float*)d_in[8];
    const float* Wo  = (const float*)d_in[9];
    const float* bo  = (const float*)d_in[10];
    float* out = (float*)d_out;

    float *qp, *kp, *vp, *cp;
    cudaGetSymbolAddress((void**)&qp, g_q);
    cudaGetSymbolAddress((void**)&kp, g_k);
    cudaGetSymbolAddress((void**)&vp, g_v);
    cudaGetSymbolAddress((void**)&cp, g_concat);

    static int smem_set = 0;
    if (!smem_set) {
        cudaFuncSetAttribute(attn_kernel,
                             cudaFuncAttributeMaxDynamicSharedMemorySize, ATTN_SMEM);
        smem_set = 1;
    }

    dim3 pgrid(NM / 128, NH / 2);
    proj_kernel<<<pgrid, 256>>>(x_q, Wq, bq, qp);
    proj_kernel<<<pgrid, 256>>>(x_k, Wk, bk, kp);
    proj_kernel<<<pgrid, 256>>>(x_v, Wv, bv, vp);

    attn_kernel<<<dim3(NS / 128, NB * NH), 256, ATTN_SMEM>>>(qp, kp, vp, cp);

    out_gemm<<<dim3(NM / 128, NFILT / 128), 256>>>(cp, Wo, bo, out);
}

// round 3
// speedup vs baseline: 1.1428x; 1.0655x over previous
#include <cuda_runtime.h>

#define NB 4
#define NS 2048
#define NF 512
#define NH 8
#define ND 64
#define NFILT 512
#define NM (NB*NS)

typedef unsigned long long u64;

// Scratch (device globals). q,k stored transposed: [B,H,D,S]. v natural: [B,H,S,D].
__device__ float g_q[(size_t)NB*NH*NS*ND];
__device__ float g_k[(size_t)NB*NH*NS*ND];
__device__ float g_v[(size_t)NB*NH*NS*ND];
__device__ float g_concat[(size_t)NB*NS*NH*ND];

// ---- packed f32x2 helpers (FFMA2 path: only reachable via PTX) -------------
__device__ __forceinline__ u64 bc2(float x) {
    u64 r; unsigned xi = __float_as_uint(x);
    asm("mov.b64 %0, {%1, %1};" : "=l"(r) : "r"(xi));
    return r;
}
__device__ __forceinline__ u64 f2(u64 a, u64 b, u64 c) {
    u64 d; asm("fma.rn.f32x2 %0, %1, %2, %3;" : "=l"(d) : "l"(a), "l"(b), "l"(c));
    return d;
}
__device__ __forceinline__ u64 m2(u64 a, u64 b) {
    u64 d; asm("mul.rn.f32x2 %0, %1, %2;" : "=l"(d) : "l"(a), "l"(b));
    return d;
}
__device__ __forceinline__ float2 up2(u64 p) {
    unsigned lo, hi;
    asm("mov.b64 {%0, %1}, %2;" : "=r"(lo), "=r"(hi) : "l"(p));
    return make_float2(__uint_as_float(lo), __uint_as_float(hi));
}

// ===========================================================================
// Warp/lane decomposition: 8 warps 4(row)x2(col); lanes 4(row)x8(col);
// thread fragment 8x8. rows = wr*32+lr*8, cols = wc*64+lc*8.
// ===========================================================================

// ---------------------------------------------------------------------------
// Per-head projection GEMM: out = X @ W[h] + bias[h]
// TRANS=1: write [B,H,D,S] (for q,k). TRANS=0: write [B,H,S,D] (for v).
// CTA tile 128(M) x 128(N = 2 heads) x 16(K). grid: (NM/128, H/2), block 256
// ---------------------------------------------------------------------------
template<int TRANS>
__global__ __launch_bounds__(256, 2) void proj_kernel(
    const float* __restrict__ X, const float* __restrict__ W,
    const float* __restrict__ bias, float* __restrict__ out)
{
    __shared__ float As[16 * 128];
    __shared__ float Bs[16 * 128];
    const int tid = threadIdx.x;
    const int w = tid >> 5, lane = tid & 31;
    const int wr = w & 3, wc = w >> 2;
    const int lr = lane >> 3, lc = lane & 7;
    const int row0 = wr * 32 + lr * 8;
    const int col0 = wc * 64 + lc * 8;
    const int m0 = blockIdx.x * 128;
    const int h0 = blockIdx.y * 2;

    const int am = tid & 127;
    const int ak = (tid >> 7) * 8;
    const float* Aptr = X + (size_t)(m0 + am) * NF + ak;
    const int bk = tid >> 4;
    const int bn = (tid & 15) * 8;
    const int bhead = h0 + (bn >> 6);
    const float* Bptr = W + (size_t)bhead * NF * ND + (size_t)bk * ND + (bn & 63);

    u64 acc2[8][4] = {};
    for (int k0 = 0; k0 < NF; k0 += 16) {
        float4 a0 = *(const float4*)(Aptr + k0);
        float4 a1 = *(const float4*)(Aptr + k0 + 4);
        float4 b0 = *(const float4*)(Bptr + (size_t)k0 * ND);
        float4 b1 = *(const float4*)(Bptr + (size_t)k0 * ND + 4);
        __syncthreads();
        As[(ak + 0) * 128 + am] = a0.x; As[(ak + 1) * 128 + am] = a0.y;
        As[(ak + 2) * 128 + am] = a0.z; As[(ak + 3) * 128 + am] = a0.w;
        As[(ak + 4) * 128 + am] = a1.x; As[(ak + 5) * 128 + am] = a1.y;
        As[(ak + 6) * 128 + am] = a1.z; As[(ak + 7) * 128 + am] = a1.w;
        *(float4*)&Bs[bk * 128 + bn] = b0;
        *(float4*)&Bs[bk * 128 + bn + 4] = b1;
        __syncthreads();
        #pragma unroll
        for (int kk = 0; kk < 16; kk++) {
            float4 x0 = *(const float4*)&As[kk * 128 + row0];
            float4 x1 = *(const float4*)&As[kk * 128 + row0 + 4];
            ulonglong2 yA = *(const ulonglong2*)&Bs[kk * 128 + col0];
            ulonglong2 yB = *(const ulonglong2*)&Bs[kk * 128 + col0 + 4];
            u64 yb2[4] = {yA.x, yA.y, yB.x, yB.y};
            float xa[8] = {x0.x, x0.y, x0.z, x0.w, x1.x, x1.y, x1.z, x1.w};
            #pragma unroll
            for (int i = 0; i < 8; i++) {
                u64 xb = bc2(xa[i]);
                #pragma unroll
                for (int jp = 0; jp < 4; jp++)
                    acc2[i][jp] = f2(xb, yb2[jp], acc2[i][jp]);
            }
        }
    }
    // unpack + bias
    const int head = h0 + wc;
    const float* bi = bias + head * ND + lc * 8;
    float4 bv0 = *(const float4*)bi;
    float4 bv1 = *(const float4*)(bi + 4);
    float bv[8] = {bv0.x, bv0.y, bv0.z, bv0.w, bv1.x, bv1.y, bv1.z, bv1.w};
    float o[8][8];
    #pragma unroll
    for (int i = 0; i < 8; i++)
        #pragma unroll
        for (int jp = 0; jp < 4; jp++) {
            float2 f = up2(acc2[i][jp]);
            o[i][2 * jp]     = f.x + bv[2 * jp];
            o[i][2 * jp + 1] = f.y + bv[2 * jp + 1];
        }
    const int mm = m0 + row0;
    const int bb = mm / NS, ss = mm % NS;
    if (TRANS) {
        // out[b,h,d,s]: float4 along s
        float* ob = out + ((size_t)(bb * NH + head) * ND + lc * 8) * NS + ss;
        #pragma unroll
        for (int j = 0; j < 8; j++) {
            float* oc = ob + (size_t)j * NS;
            *(float4*)(oc)     = make_float4(o[0][j], o[1][j], o[2][j], o[3][j]);
            *(float4*)(oc + 4) = make_float4(o[4][j], o[5][j], o[6][j], o[7][j]);
        }
    } else {
        float* ob = out + ((size_t)(bb * NH + head) * NS + ss) * ND + lc * 8;
        #pragma unroll
        for (int i = 0; i < 8; i++) {
            *(float4*)(ob + (size_t)i * ND) =
                make_float4(o[i][0], o[i][1], o[i][2], o[i][3]);
            *(float4*)(ob + (size_t)i * ND + 4) =
                make_float4(o[i][4], o[i][5], o[i][6], o[i][7]);
        }
    }
}

// ---------------------------------------------------------------------------
// Output GEMM: C = A[NM,512] @ W[512,512] + bias. Tile 128x128x16.
// ---------------------------------------------------------------------------
__global__ __launch_bounds__(256, 2) void out_gemm(
    const float* __restrict__ A, const float* __restrict__ W,
    const float* __restrict__ bias, float* __restrict__ C)
{
    __shared__ float As[16 * 128];
    __shared__ float Bs[16 * 128];
    const int tid = threadIdx.x;
    const int w = tid >> 5, lane = tid & 31;
    const int wr = w & 3, wc = w >> 2;
    const int lr = lane >> 3, lc = lane & 7;
    const int row0 = wr * 32 + lr * 8;
    const int col0 = wc * 64 + lc * 8;
    const int m0 = blockIdx.x * 128;
    const int n0 = blockIdx.y * 128;

    const int am = tid & 127;
    const int ak = (tid >> 7) * 8;
    const float* Aptr = A + (size_t)(m0 + am) * NFILT + ak;
    const int bk = tid >> 4;
    const int bn = (tid & 15) * 8;
    const float* Bptr = W + (size_t)bk * NFILT + n0 + bn;

    u64 acc2[8][4] = {};
    for (int k0 = 0; k0 < NFILT; k0 += 16) {
        float4 a0 = *(const float4*)(Aptr + k0);
        float4 a1 = *(const float4*)(Aptr + k0 + 4);
        float4 b0 = *(const float4*)(Bptr + (size_t)k0 * NFILT);
        float4 b1 = *(const float4*)(Bptr + (size_t)k0 * NFILT + 4);
        __syncthreads();
        As[(ak + 0) * 128 + am] = a0.x; As[(ak + 1) * 128 + am] = a0.y;
        As[(ak + 2) * 128 + am] = a0.z; As[(ak + 3) * 128 + am] = a0.w;
        As[(ak + 4) * 128 + am] = a1.x; As[(ak + 5) * 128 + am] = a1.y;
        As[(ak + 6) * 128 + am] = a1.z; As[(ak + 7) * 128 + am] = a1.w;
        *(float4*)&Bs[bk * 128 + bn] = b0;
        *(float4*)&Bs[bk * 128 + bn + 4] = b1;
        __syncthreads();
        #pragma unroll
        for (int kk = 0; kk < 16; kk++) {
            float4 x0 = *(const float4*)&As[kk * 128 + row0];
            float4 x1 = *(const float4*)&As[kk * 128 + row0 + 4];
            ulonglong2 yA = *(const ulonglong2*)&Bs[kk * 128 + col0];
            ulonglong2 yB = *(const ulonglong2*)&Bs[kk * 128 + col0 + 4];
            u64 yb2[4] = {yA.x, yA.y, yB.x, yB.y};
            float xa[8] = {x0.x, x0.y, x0.z, x0.w, x1.x, x1.y, x1.z, x1.w};
            #pragma unroll
            for (int i = 0; i < 8; i++) {
                u64 xb = bc2(xa[i]);
                #pragma unroll
                for (int jp = 0; jp < 4; jp++)
                    acc2[i][jp] = f2(xb, yb2[jp], acc2[i][jp]);
            }
        }
    }
    const float* bi = bias + n0 + col0;
    float4 bv0 = *(const float4*)bi;
    float4 bv1 = *(const float4*)(bi + 4);
    float bv[8] = {bv0.x, bv0.y, bv0.z, bv0.w, bv1.x, bv1.y, bv1.z, bv1.w};
    float* cb = C + (size_t)(m0 + row0) * NFILT + n0 + col0;
    #pragma unroll
    for (int i = 0; i < 8; i++) {
        float o[8];
        #pragma unroll
        for (int jp = 0; jp < 4; jp++) {
            float2 f = up2(acc2[i][jp]);
            o[2 * jp] = f.x + bv[2 * jp];
            o[2 * jp + 1] = f.y + bv[2 * jp + 1];
        }
        *(float4*)(cb + (size_t)i * NFILT) = make_float4(o[0], o[1], o[2], o[3]);
        *(float4*)(cb + (size_t)i * NFILT + 4) = make_float4(o[4], o[5], o[6], o[7]);
    }
}

// ---------------------------------------------------------------------------
// Flash attention: 128x128 tiles. q,k arrive d-major [B,H,D,S] -> straight
// float4 row copies into smem (no transposed scalar stores). P swizzled.
// smem: Qs[64][128] | KP[128][128] | Vs[128][64] | redm[256] | reds[256]
// grid: (NS/128, B*H), block 256
// ---------------------------------------------------------------------------
__global__ __launch_bounds__(256, 1) void attn_kernel(
    const float* __restrict__ qt, const float* __restrict__ kt_,
    const float* __restrict__ v, float* __restrict__ concat)
{
    extern __shared__ float sm[];
    float* Qs   = sm;                    // 8192
    float* KP   = sm + 8192;             // 16384
    float* Vs   = sm + 8192 + 16384;     // 8192
    float* redm = Vs + 8192;             // 256
    float* reds = redm + 256;            // 256

    const int tid = threadIdx.x;
    const int w = tid >> 5, lane = tid & 31;
    const int wr = w & 3, wc = w >> 2;
    const int lr = lane >> 3, lc = lane & 7;
    const int row0 = wr * 32 + lr * 8;
    const int colS = wc * 64 + lc * 8;
    const int colO = wc * 32 + lc * 4;
    const int swz = lr << 2;

    const int bh = blockIdx.y, bb = bh >> 3, hh = bh & 7;
    const int s0 = blockIdx.x * 128;
    const float* qb = qt  + (size_t)bh * ND * NS;   // [d][s]
    const float* kb = kt_ + (size_t)bh * ND * NS;   // [d][s]
    const float* vb = v   + (size_t)bh * NS * ND;   // [s][d]

    // Load Q tile [64][128] (d-major in gmem already), scale by 1/8
    {
        #pragma unroll
        for (int u = 0; u < 8; u++) {
            int f4 = u * 256 + tid;            // 0..2047
            int row = f4 >> 5, c4 = (f4 & 31) << 2;
            float4 a = *(const float4*)(qb + (size_t)row * NS + s0 + c4);
            *(float4*)&Qs[row * 128 + c4] =
                make_float4(a.x * 0.125f, a.y * 0.125f, a.z * 0.125f, a.w * 0.125f);
        }
    }

    float m_i[8], l_i[8];
    u64 O2[8][2] = {};
    #pragma unroll
    for (int i = 0; i < 8; i++) { m_i[i] = -1e30f; l_i[i] = 0.0f; }

    for (int ktile = 0; ktile < NS; ktile += 128) {
        __syncthreads();
        // K tile [64][128] from d-major gmem
        #pragma unroll
        for (int u = 0; u < 8; u++) {
            int f4 = u * 256 + tid;
            int row = f4 >> 5, c4 = (f4 & 31) << 2;
            *(float4*)&KP[row * 128 + c4] =
                *(const float4*)(kb + (size_t)row * NS + ktile + c4);
        }
        // V tile straight copy
        {
            const float4* src = (const float4*)(vb + (size_t)ktile * ND);
            float4* dst = (float4*)Vs;
            #pragma unroll
            for (int i2 = 0; i2 < 8; i2++) dst[tid + i2 * 256] = src[tid + i2 * 256];
        }
        __syncthreads();

        // S = (Q*scale) @ K^T : packed 8x(4x2) fragment
        u64 sacc2[8][4] = {};
        #pragma unroll 8
        for (int d = 0; d < 64; d++) {
            float4 x0 = *(const float4*)&Qs[d * 128 + row0];
            float4 x1 = *(const float4*)&Qs[d * 128 + row0 + 4];
            ulonglong2 yA = *(const ulonglong2*)&KP[d * 128 + colS];
            ulonglong2 yB = *(const ulonglong2*)&KP[d * 128 + colS + 4];
            u64 yb2[4] = {yA.x, yA.y, yB.x, yB.y};
            float xa[8] = {x0.x, x0.y, x0.z, x0.w, x1.x, x1.y, x1.z, x1.w};
            #pragma unroll
            for (int i = 0; i < 8; i++) {
                u64 xb = bc2(xa[i]);
                #pragma unroll
                for (int jp = 0; jp < 4; jp++)
                    sacc2[i][jp] = f2(xb, yb2[jp], sacc2[i][jp]);
            }
        }
        float sacc[8][8];
        #pragma unroll
        for (int i = 0; i < 8; i++)
            #pragma unroll
            for (int jp = 0; jp < 4; jp++) {
                float2 f = up2(sacc2[i][jp]);
                sacc[i][2 * jp] = f.x; sacc[i][2 * jp + 1] = f.y;
            }

        // Row max: thread -> lanes (lc) -> warp-cols (smem)
        float pm[8];
        #pragma unroll
        for (int i = 0; i < 8; i++) {
            float r = fmaxf(fmaxf(fmaxf(sacc[i][0], sacc[i][1]),
                                  fmaxf(sacc[i][2], sacc[i][3])),
                            fmaxf(fmaxf(sacc[i][4], sacc[i][5]),
                                  fmaxf(sacc[i][6], sacc[i][7])));
            r = fmaxf(r, __shfl_xor_sync(0xffffffffu, r, 1));
            r = fmaxf(r, __shfl_xor_sync(0xffffffffu, r, 2));
            r = fmaxf(r, __shfl_xor_sync(0xffffffffu, r, 4));
            pm[i] = r;
        }
        if (lc == 0) {
            #pragma unroll
            for (int i = 0; i < 8; i++) redm[wc * 128 + row0 + i] = pm[i];
        }
        __syncthreads();

        float alpha[8];
        #pragma unroll
        for (int i = 0; i < 8; i++) {
            float mt = fmaxf(redm[row0 + i], redm[128 + row0 + i]);
            float mn = fmaxf(m_i[i], mt);
            alpha[i] = __expf(m_i[i] - mn);
            m_i[i] = mn;
        }
        float ps[8];
        #pragma unroll
        for (int i = 0; i < 8; i++) {
            float s = 0.0f;
            #pragma unroll
            for (int j = 0; j < 8; j++) {
                float p = __expf(sacc[i][j] - m_i[i]);
                sacc[i][j] = p;
                s += p;
            }
            s += __shfl_xor_sync(0xffffffffu, s, 1);
            s += __shfl_xor_sync(0xffffffffu, s, 2);
            s += __shfl_xor_sync(0xffffffffu, s, 4);
            ps[i] = s;
        }
        if (lc == 0) {
            #pragma unroll
            for (int i = 0; i < 8; i++) reds[wc * 128 + row0 + i] = ps[i];
        }
        // Store P (swizzled by lr*4)
        #pragma unroll
        for (int i = 0; i < 8; i++) {
            int r = row0 + i;
            *(float4*)&KP[r * 128 + ((colS) ^ swz)] =
                make_float4(sacc[i][0], sacc[i][1], sacc[i][2], sacc[i][3]);
            *(float4*)&KP[r * 128 + ((colS + 4) ^ swz)] =
                make_float4(sacc[i][4], sacc[i][5], sacc[i][6], sacc[i][7]);
        }
        // Rescale O accumulators (packed)
        #pragma unroll
        for (int i = 0; i < 8; i++) {
            u64 a2 = bc2(alpha[i]);
            O2[i][0] = m2(a2, O2[i][0]);
            O2[i][1] = m2(a2, O2[i][1]);
        }
        __syncthreads();
        #pragma unroll
        for (int i = 0; i < 8; i++)
            l_i[i] = l_i[i] * alpha[i] + reds[row0 + i] + reds[128 + row0 + i];

        // O += P @ V (packed)
        #pragma unroll 4
        for (int t0 = 0; t0 < 128; t0 += 4) {
            const int tx = t0 ^ swz;
            float pa[8][4];
            #pragma unroll
            for (int i = 0; i < 8; i++) {
                float4 p4 = *(const float4*)&KP[(row0 + i) * 128 + tx];
                pa[i][0] = p4.x; pa[i][1] = p4.y; pa[i][2] = p4.z; pa[i][3] = p4.w;
            }
            #pragma unroll
            for (int tt = 0; tt < 4; tt++) {
                ulonglong2 v2 = *(const ulonglong2*)&Vs[(t0 + tt) * 64 + colO];
                #pragma unroll
                for (int i = 0; i < 8; i++) {
                    u64 pb = bc2(pa[i][tt]);
                    O2[i][0] = f2(pb, v2.x, O2[i][0]);
                    O2[i][1] = f2(pb, v2.y, O2[i][1]);
                }
            }
        }
    }

    // Normalize, write concat [B, S, H*DV]
    float* ob = concat + ((size_t)bb * NS + s0 + row0) * (NH * ND) + hh * ND + colO;
    #pragma unroll
    for (int i = 0; i < 8; i++) {
        float inv = 1.0f / l_i[i];
        float2 f0 = up2(O2[i][0]);
        float2 f1 = up2(O2[i][1]);
        *(float4*)(ob + (size_t)i * (NH * ND)) =
            make_float4(f0.x * inv, f0.y * inv, f1.x * inv, f1.y * inv);
    }
}

// ---------------------------------------------------------------------------
#define ATTN_SMEM ((8192 + 16384 + 8192 + 512) * 4)

extern "C" void kernel_launch(void* const* d_in, const int* in_sizes, int n_in,
                              void* d_out, int out_size)
{
    (void)in_sizes; (void)n_in; (void)out_size;
    const float* x_q = (const float*)d_in[0];
    const float* x_k = (const float*)d_in[1];
    const float* x_v = (const float*)d_in[2];
    const float* Wq  = (const float*)d_in[3];
    const float* bq  = (const float*)d_in[4];
    const float* Wk  = (const float*)d_in[5];
    const float* bk  = (const float*)d_in[6];
    const float* Wv  = (const float*)d_in[7];
    const float* bv  = (const float*)d_in[8];
    const float* Wo  = (const float*)d_in[9];
    const float* bo  = (const float*)d_in[10];
    float* out = (float*)d_out;

    float *qp, *kp, *vp, *cp;
    cudaGetSymbolAddress((void**)&qp, g_q);
    cudaGetSymbolAddress((void**)&kp, g_k);
    cudaGetSymbolAddress((void**)&vp, g_v);
    cudaGetSymbolAddress((void**)&cp, g_concat);

    static int smem_set = 0;
    if (!smem_set) {
        cudaFuncSetAttribute(attn_kernel,
                             cudaFuncAttributeMaxDynamicSharedMemorySize, ATTN_SMEM);
        smem_set = 1;
    }

    dim3 pgrid(NM / 128, NH / 2);
    proj_kernel<1><<<pgrid, 256>>>(x_q, Wq, bq, qp);
    proj_kernel<1><<<pgrid, 256>>>(x_k, Wk, bk, kp);
    proj_kernel<0><<<pgrid, 256>>>(x_v, Wv, bv, vp);

    attn_kernel<<<dim3(NS / 128, NB * NH), 256, ATTN_SMEM>>>(qp, kp, vp, cp);

    out_gemm<<<dim3(NM / 128, NFILT / 128), 256>>>(cp, Wo, bo, out);
}